// round 17
// baseline (speedup 1.0000x reference)
#include <cuda_runtime.h>
#include <cuda_fp16.h>
#include <cstdint>

// ============================================================================
// Warp-specialized fused tensor-core GRU.
//   Consumer warps 0-3: gh MMAs + gates + h recurrence (6 n-tiles each).
//   Producer warps 4-7: gx(t+1) MMAs + x load/convert (6 n-tiles each).
//   gx handoff via double-buffered smem with identical C-fragment layouts.
// fp16: x single, wih single, h hi+lo, whh hi+lo. r,z prescaled by 0.5.
// B=2048, T=256, F=128, H=64. 128 blocks x 256 threads; 16 rows/block.
// ============================================================================

#define Bn 2048
#define Tn 256
#define Fn 128
#define Hn 64
#define ROWS 16
#define NTH 256

// smem offsets (bytes)
#define WIH_H 0                 // 192 x 272 fp16
#define WHH_H 52224             // 192 x 144 fp16 hi
#define WHH_L 79872             // 192 x 144 fp16 lo
#define XB    107520            // x fp16: 2 bufs x 4352
#define XSZ   4352
#define HBB   116224            // h fp16: hi bufs [2] then lo bufs [2], 2304 each
#define HSZ   2304
#define HLO   4608
#define GXB   125440            // gx fp32: 2 bufs x 12288 (24 tiles x 512B)
#define GXSZ  12288
#define HF    150016            // fp32 h_last: 16 x 68
#define SMEMB 154368

#define BAR_ALL()  asm volatile("bar.sync 0, 256;" ::: "memory")
#define BAR_PROD() asm volatile("bar.sync 1, 128;" ::: "memory")
#define BAR_CONS() asm volatile("bar.sync 2, 128;" ::: "memory")

__device__ __forceinline__ uint32_t smem_u32(const void* p) {
    uint32_t a;
    asm("{ .reg .u64 t; cvta.to.shared.u64 t, %1; cvt.u32.u64 %0, t; }"
        : "=r"(a) : "l"(p));
    return a;
}
__device__ __forceinline__ void ldsm4(uint32_t* r, uint32_t addr) {
    asm volatile("ldmatrix.sync.aligned.m8n8.x4.shared.b16 {%0,%1,%2,%3}, [%4];"
        : "=r"(r[0]), "=r"(r[1]), "=r"(r[2]), "=r"(r[3]) : "r"(addr));
}
__device__ __forceinline__ void ldsm2(uint32_t* r, uint32_t addr) {
    asm volatile("ldmatrix.sync.aligned.m8n8.x2.shared.b16 {%0,%1}, [%2];"
        : "=r"(r[0]), "=r"(r[1]) : "r"(addr));
}
__device__ __forceinline__ void mma16816(float* c, const uint32_t* a,
                                         uint32_t b0, uint32_t b1) {
    asm volatile(
        "mma.sync.aligned.m16n8k16.row.col.f32.f16.f16.f32 "
        "{%0,%1,%2,%3}, {%4,%5,%6,%7}, {%8,%9}, {%0,%1,%2,%3};"
        : "+f"(c[0]), "+f"(c[1]), "+f"(c[2]), "+f"(c[3])
        : "r"(a[0]), "r"(a[1]), "r"(a[2]), "r"(a[3]), "r"(b0), "r"(b1));
}
__device__ __forceinline__ uint32_t packh2(float a, float b) {
    __half2 h = __floats2half2_rn(a, b);
    return *(uint32_t*)&h;
}
__device__ __forceinline__ void store_w_hi(char* sm, int off_hi, int boff,
                                           float4 v, float s) {
    *(uint2*)(sm + off_hi + boff) =
        make_uint2(packh2(v.x * s, v.y * s), packh2(v.z * s, v.w * s));
}
__device__ __forceinline__ void split_store_w(char* sm, int off_hi, int off_lo,
                                              int boff, float4 v, float s) {
    float vx = v.x * s, vy = v.y * s, vz = v.z * s, vw = v.w * s;
    __half2 h01 = __floats2half2_rn(vx, vy);
    __half2 h23 = __floats2half2_rn(vz, vw);
    *(uint2*)(sm + off_hi + boff) = make_uint2(*(uint32_t*)&h01, *(uint32_t*)&h23);
    float l0 = vx - __half2float(__low2half(h01));
    float l1 = vy - __half2float(__high2half(h01));
    float l2 = vz - __half2float(__low2half(h23));
    float l3 = vw - __half2float(__high2half(h23));
    *(uint2*)(sm + off_lo + boff) = make_uint2(packh2(l0, l1), packh2(l2, l3));
}
__device__ __forceinline__ void store_x16(char* sm, int off, int boff,
                                          float4 a, float4 b) {
    uint4 u;
    u.x = packh2(a.x, a.y);
    u.y = packh2(a.z, a.w);
    u.z = packh2(b.x, b.y);
    u.w = packh2(b.z, b.w);
    *(uint4*)(sm + off + boff) = u;
}
__device__ __forceinline__ float tanh_ap(float v) {
    float r;
    asm("tanh.approx.f32 %0, %1;" : "=f"(r) : "f"(v));
    return r;
}

__global__ void __launch_bounds__(NTH, 1)
gru_fused_tc(const float* __restrict__ x,
             const float* __restrict__ w_ih,
             const float* __restrict__ w_hh,
             const float* __restrict__ b_ih,
             const float* __restrict__ b_hh,
             const float* __restrict__ fc_w,
             const float* __restrict__ fc_b,
             float* __restrict__ out) {
    extern __shared__ char sm[];
    const uint32_t sb = smem_u32(sm);
    const int tid = threadIdx.x;
    const int w   = tid >> 5;
    const int l   = tid & 31;
    const int wg  = w & 3;           // SMSP pair index
    const int r0  = blockIdx.x * ROWS;
    const int lq    = l & 15;
    const int mrow  = (l & 7) + ((l >> 3) & 1) * 8;
    const int khalf = (l >> 4) & 1;
    const int r_l   = l >> 2;
    const int c0    = 2 * (l & 3);
    const int ubase = 16 * wg + c0;  // u for p=0; p=1 adds 8

    // ---- weights -> smem (r,z rows prescaled by 0.5; exact in fp16) ----
    {
        const float4* w4 = (const float4*)w_ih;
        #pragma unroll
        for (int j = 0; j < 24; ++j) {
            int idx = j * 256 + tid;
            int row = idx >> 5, c4 = idx & 31;
            float s = (row < 128) ? 0.5f : 1.0f;
            store_w_hi(sm, WIH_H, row * 272 + c4 * 8, w4[idx], s);
        }
        const float4* v4 = (const float4*)w_hh;
        #pragma unroll
        for (int j = 0; j < 12; ++j) {
            int idx = j * 256 + tid;
            int row = idx >> 4, c4 = idx & 15;
            float s = (row < 128) ? 0.5f : 1.0f;
            split_store_w(sm, WHH_H, WHH_L, row * 144 + c4 * 8, v4[idx], s);
        }
        for (int i = tid; i < (4 * HSZ) / 4; i += NTH)
            *(uint32_t*)(sm + HBB + i * 4) = 0u;
    }
    __syncthreads();

    if (w >= 4) {
        // ======================= PRODUCER (warps 4-7) =======================
        // per-tile biases folded into gx accumulators (r,z halved)
        float bias[6][2];
        #pragma unroll
        for (int p = 0; p < 2; ++p) {
            int u = ubase + 8 * p;
            bias[0 + p][0] = 0.5f * (b_ih[u] + b_hh[u]);
            bias[0 + p][1] = 0.5f * (b_ih[u + 1] + b_hh[u + 1]);
            bias[2 + p][0] = 0.5f * (b_ih[64 + u] + b_hh[64 + u]);
            bias[2 + p][1] = 0.5f * (b_ih[64 + u + 1] + b_hh[64 + u + 1]);
            bias[4 + p][0] = b_ih[128 + u];
            bias[4 + p][1] = b_ih[128 + u + 1];
        }
        // resident wih B-fragments for tiles {2wg,2wg+1, 8+2wg,8+2wg+1, 16+2wg,16+2wg+1}
        uint32_t wf[6][8][2];
        #pragma unroll
        for (int j = 0; j < 6; ++j) {
            int tau = (j >> 1) * 8 + 2 * wg + (j & 1);
            #pragma unroll
            for (int ks = 0; ks < 8; ++ks)
                ldsm2(wf[j][ks], sb + WIH_H +
                      (uint32_t)((tau * 8 + (lq & 7)) * 272 + ks * 32 + (lq >> 3) * 16));
        }
        // x preload t=0 -> buf0, t=1 -> buf1 (128 producer threads)
        const int ptid = tid - 128;
        const int prow = ptid >> 3;
        const int pc4  = (ptid & 7) * 4;
        const float4* x4 = (const float4*)x;
        const size_t xrow = (size_t)(r0 + prow) * (Tn * Fn / 4);
        #pragma unroll
        for (int b = 0; b < 2; ++b) {
            float4 v0 = x4[xrow + b * 32 + pc4];
            float4 v1 = x4[xrow + b * 32 + pc4 + 1];
            float4 v2 = x4[xrow + b * 32 + pc4 + 2];
            float4 v3 = x4[xrow + b * 32 + pc4 + 3];
            store_x16(sm, XB + b * XSZ, prow * 272 + pc4 * 8, v0, v1);
            store_x16(sm, XB + b * XSZ, prow * 272 + (pc4 + 2) * 8, v2, v3);
        }
        BAR_PROD();   // x buffers visible to all producer warps

        const uint32_t aX = (uint32_t)(mrow * 272 + khalf * 16);

        // prologue: gx(0) -> gxbuf[0]
        {
            float acc[6][4];
            #pragma unroll
            for (int j = 0; j < 6; ++j) {
                acc[j][0] = bias[j][0]; acc[j][1] = bias[j][1];
                acc[j][2] = bias[j][0]; acc[j][3] = bias[j][1];
            }
            #pragma unroll
            for (int ks = 0; ks < 8; ++ks) {
                uint32_t ah[4];
                ldsm4(ah, sb + XB + aX + ks * 32);
                #pragma unroll
                for (int j = 0; j < 6; ++j)
                    mma16816(acc[j], ah, wf[j][ks][0], wf[j][ks][1]);
            }
            #pragma unroll
            for (int j = 0; j < 6; ++j)
                *(float4*)(sm + GXB + (wg * 6 + j) * 512 + l * 16) =
                    make_float4(acc[j][0], acc[j][1], acc[j][2], acc[j][3]);
        }
        BAR_ALL();

        for (int t = 0; t < Tn; ++t) {
            const int cur = t & 1, nxt = cur ^ 1;
            float4 p0, p1, p2, p3;
            const bool pf2 = (t + 2 < Tn);
            if (pf2) {
                p0 = x4[xrow + (size_t)(t + 2) * 32 + pc4];
                p1 = x4[xrow + (size_t)(t + 2) * 32 + pc4 + 1];
                p2 = x4[xrow + (size_t)(t + 2) * 32 + pc4 + 2];
                p3 = x4[xrow + (size_t)(t + 2) * 32 + pc4 + 3];
            }
            if (t + 1 < Tn) {
                float acc[6][4];
                #pragma unroll
                for (int j = 0; j < 6; ++j) {
                    acc[j][0] = bias[j][0]; acc[j][1] = bias[j][1];
                    acc[j][2] = bias[j][0]; acc[j][3] = bias[j][1];
                }
                #pragma unroll
                for (int ks = 0; ks < 8; ++ks) {
                    uint32_t ah[4];
                    ldsm4(ah, sb + XB + nxt * XSZ + aX + ks * 32);
                    #pragma unroll
                    for (int j = 0; j < 6; ++j)
                        mma16816(acc[j], ah, wf[j][ks][0], wf[j][ks][1]);
                }
                if (pf2) {
                    store_x16(sm, XB + cur * XSZ, prow * 272 + pc4 * 8, p0, p1);
                    store_x16(sm, XB + cur * XSZ, prow * 272 + (pc4 + 2) * 8, p2, p3);
                }
                #pragma unroll
                for (int j = 0; j < 6; ++j)
                    *(float4*)(sm + GXB + nxt * GXSZ + (wg * 6 + j) * 512 + l * 16) =
                        make_float4(acc[j][0], acc[j][1], acc[j][2], acc[j][3]);
            }
            BAR_ALL();
        }
    } else {
        // ======================= CONSUMER (warps 0-3) =======================
        float bn_h[2][2];
        #pragma unroll
        for (int p = 0; p < 2; ++p) {
            int u = ubase + 8 * p;
            bn_h[p][0] = b_hh[128 + u];
            bn_h[p][1] = b_hh[128 + u + 1];
        }
        // resident whh hi/lo B-fragments (same tile set as paired producer)
        uint32_t whH[6][4][2], whL[6][4][2];
        #pragma unroll
        for (int j = 0; j < 6; ++j) {
            int tau = (j >> 1) * 8 + 2 * wg + (j & 1);
            #pragma unroll
            for (int ks = 0; ks < 4; ++ks) {
                uint32_t off = (uint32_t)((tau * 8 + (lq & 7)) * 144
                               + ks * 32 + (lq >> 3) * 16);
                ldsm2(whH[j][ks], sb + WHH_H + off);
                ldsm2(whL[j][ks], sb + WHH_L + off);
            }
        }
        const uint32_t aH = (uint32_t)(mrow * 144 + khalf * 16);
        float hold[2][4];
        #pragma unroll
        for (int p = 0; p < 2; ++p)
            #pragma unroll
            for (int i = 0; i < 4; ++i) hold[p][i] = 0.f;

        BAR_ALL();

        for (int t = 0; t < Tn; ++t) {
            const int cur = t & 1, nxt = cur ^ 1;

            // gx(t) from producer buffer (identical C-fragment layout)
            float4 gx[6];
            #pragma unroll
            for (int j = 0; j < 6; ++j)
                gx[j] = *(const float4*)(sm + GXB + cur * GXSZ
                                         + (wg * 6 + j) * 512 + l * 16);

            float gh[6][4];
            #pragma unroll
            for (int j = 0; j < 4; ++j)
                #pragma unroll
                for (int i = 0; i < 4; ++i) gh[j][i] = 0.f;
            gh[4][0] = bn_h[0][0]; gh[4][1] = bn_h[0][1];
            gh[4][2] = bn_h[0][0]; gh[4][3] = bn_h[0][1];
            gh[5][0] = bn_h[1][0]; gh[5][1] = bn_h[1][1];
            gh[5][2] = bn_h[1][0]; gh[5][3] = bn_h[1][1];

            const uint32_t hh = sb + HBB + cur * HSZ + aH;
            const uint32_t hl = hh + HLO;
            #pragma unroll
            for (int q = 0; q < 4; ++q) {
                uint32_t hah[4], hal[4];
                ldsm4(hah, hh + q * 32);
                ldsm4(hal, hl + q * 32);
                #pragma unroll
                for (int j = 0; j < 6; ++j)
                    mma16816(gh[j], hah, whH[j][q][0], whH[j][q][1]);
                #pragma unroll
                for (int j = 0; j < 6; ++j)
                    mma16816(gh[j], hah, whL[j][q][0], whL[j][q][1]);
                #pragma unroll
                for (int j = 0; j < 6; ++j)
                    mma16816(gh[j], hal, whH[j][q][0], whH[j][q][1]);
            }

            // gates + h update (prescale baked into weights/biases)
            #pragma unroll
            for (int p = 0; p < 2; ++p) {
                #pragma unroll
                for (int i = 0; i < 4; ++i) {
                    float gr = ((const float*)&gx[0 + p])[i];
                    float gz = ((const float*)&gx[2 + p])[i];
                    float gn = ((const float*)&gx[4 + p])[i];
                    float rr = fmaf(0.5f, tanh_ap(gh[0 + p][i] + gr), 0.5f);
                    float zz = fmaf(0.5f, tanh_ap(gh[2 + p][i] + gz), 0.5f);
                    float nn = tanh_ap(gn + rr * gh[4 + p][i]);
                    hold[p][i] = fmaf(zz, hold[p][i] - nn, nn);
                }
            }

            // store h(t+1) fp16 hi/lo
            #pragma unroll
            for (int p = 0; p < 2; ++p) {
                int uc = ubase + 8 * p;
                __half2 a2 = __floats2half2_rn(hold[p][0], hold[p][1]);
                *(uint32_t*)(sm + HBB + nxt * HSZ + r_l * 144 + uc * 2) =
                    *(uint32_t*)&a2;
                float e0 = hold[p][0] - __half2float(__low2half(a2));
                float e1 = hold[p][1] - __half2float(__high2half(a2));
                *(uint32_t*)(sm + HBB + HLO + nxt * HSZ + r_l * 144 + uc * 2) =
                    packh2(e0, e1);
                __half2 b2 = __floats2half2_rn(hold[p][2], hold[p][3]);
                *(uint32_t*)(sm + HBB + nxt * HSZ + (r_l + 8) * 144 + uc * 2) =
                    *(uint32_t*)&b2;
                float e2 = hold[p][2] - __half2float(__low2half(b2));
                float e3 = hold[p][3] - __half2float(__high2half(b2));
                *(uint32_t*)(sm + HBB + HLO + nxt * HSZ + (r_l + 8) * 144 + uc * 2) =
                    packh2(e2, e3);
            }

            BAR_ALL();
        }

        // final FC (consumers hold h_last)
        float* hf = (float*)(sm + HF);
        #pragma unroll
        for (int p = 0; p < 2; ++p) {
            int uc = ubase + 8 * p;
            hf[r_l * 68 + uc]           = hold[p][0];
            hf[r_l * 68 + uc + 1]       = hold[p][1];
            hf[(r_l + 8) * 68 + uc]     = hold[p][2];
            hf[(r_l + 8) * 68 + uc + 1] = hold[p][3];
        }
        BAR_CONS();
        if (tid < ROWS) {
            float s = fc_b[0];
            #pragma unroll 8
            for (int j = 0; j < Hn; ++j)
                s += hf[tid * 68 + j] * fc_w[j];
            out[r0 + tid] = s;
        }
    }
}

extern "C" void kernel_launch(void* const* d_in, const int* in_sizes, int n_in,
                              void* d_out, int out_size) {
    const float* x    = (const float*)d_in[0];
    const float* w_ih = (const float*)d_in[1];
    const float* w_hh = (const float*)d_in[2];
    const float* b_ih = (const float*)d_in[3];
    const float* b_hh = (const float*)d_in[4];
    const float* fc_w = (const float*)d_in[5];
    const float* fc_b = (const float*)d_in[6];
    float* out = (float*)d_out;

    cudaFuncSetAttribute(gru_fused_tc,
                         cudaFuncAttributeMaxDynamicSharedMemorySize, SMEMB);
    gru_fused_tc<<<Bn / ROWS, NTH, SMEMB>>>(
        x, w_ih, w_hh, b_ih, b_hh, fc_w, fc_b, out);
}